// round 1
// baseline (speedup 1.0000x reference)
#include <cuda_runtime.h>
#include <cuda_bf16.h>
#include <cstdint>

// Problem constants (from reference: B=4, N=50000, E=800000, C_IN=C_OUT=128)
#define GB 4
#define GC 128
#define MAXN 50000

// Scratch: agg[b][n][c]  (4*50000*128 floats = 102.4 MB, static device alloc)
__device__ float g_agg[(size_t)GB * MAXN * GC];

// ---------------------------------------------------------------------------
// Kernel 1: zero the aggregation scratch
// ---------------------------------------------------------------------------
__global__ void zero_agg_kernel(size_t n_float4) {
    size_t i = (size_t)blockIdx.x * blockDim.x + threadIdx.x;
    if (i < n_float4) {
        ((float4*)g_agg)[i] = make_float4(0.f, 0.f, 0.f, 0.f);
    }
}

// ---------------------------------------------------------------------------
// Kernel 2: edge scatter with atomics.
// One thread per (edge, batch, 4-float chunk). 32 consecutive threads cover
// one (edge,batch) row of 128 floats -> fully coalesced 512B gather of x.
// ---------------------------------------------------------------------------
__global__ void scatter_kernel(const float* __restrict__ x,
                               const int* __restrict__ erow,
                               const int* __restrict__ ecol,
                               const float* __restrict__ evals,
                               int E, int N) {
    long long idx = (long long)blockIdx.x * blockDim.x + threadIdx.x;
    long long total = (long long)E * (GB * (GC / 4));   // E * 4 * 32
    if (idx >= total) return;

    int chunk = (int)(idx & 31);          // which float4 of the 128-float row
    int b     = (int)((idx >> 5) & 3);    // batch
    int e     = (int)(idx >> 7);          // edge

    int r = erow[e];
    int c = ecol[e];
    float v = evals[e];

    const float4 xv = ((const float4*)(x + ((size_t)b * N + c) * GC))[chunk];
    float* dst = g_agg + ((size_t)b * N + r) * GC + chunk * 4;

    atomicAdd(dst + 0, v * xv.x);
    atomicAdd(dst + 1, v * xv.y);
    atomicAdd(dst + 2, v * xv.z);
    atomicAdd(dst + 3, v * xv.w);
}

// ---------------------------------------------------------------------------
// Kernel 3: fused dense GEMM (agg @ W) + bias + ReLU.
// Block = 256 threads (8 warps). Block handles 64 rows; each warp handles 8
// rows simultaneously (amortizes the W smem read 8x). Each thread computes 4
// output columns (lane*4 .. lane*4+3) for its 8 rows.
// Dynamic smem: W (64KB) + 64 agg rows (32KB) + bias (512B).
// ---------------------------------------------------------------------------
#define ROWS_PER_BLOCK 64
#define GEMM_THREADS 256

__global__ void gemm_bias_relu_kernel(const float* __restrict__ W,
                                      const float* __restrict__ bias,
                                      float* __restrict__ out,
                                      int total_rows) {
    extern __shared__ float smem[];
    float* sW    = smem;                     // 128*128
    float* sRow  = smem + GC * GC;           // 64*128
    float* sBias = sRow + ROWS_PER_BLOCK * GC; // 128

    int tid = threadIdx.x;
    int warp = tid >> 5;
    int lane = tid & 31;

    // Cooperative load of W (16384 floats -> 64 float4 per thread)
    {
        const float4* Wv = (const float4*)W;
        float4* sWv = (float4*)sW;
        #pragma unroll
        for (int i = 0; i < (GC * GC / 4) / GEMM_THREADS; i++) {
            sWv[tid + i * GEMM_THREADS] = Wv[tid + i * GEMM_THREADS];
        }
        if (tid < GC) sBias[tid] = bias[tid];
    }

    int row_base = blockIdx.x * ROWS_PER_BLOCK;

    // Cooperative load of 64 agg rows (8192 floats = 2048 float4)
    {
        const float4* Av = (const float4*)(g_agg + (size_t)row_base * GC);
        float4* sRv = (float4*)sRow;
        int nvec = ROWS_PER_BLOCK * GC / 4;  // 2048
        for (int i = tid; i < nvec; i += GEMM_THREADS) {
            int row = row_base + (i * 4) / GC;
            if (row < total_rows) sRv[i] = Av[i];
        }
    }
    __syncthreads();

    // Each warp: 8 rows, each thread: 4 columns.
    int r0 = warp * 8;  // local row offset within block

    float4 acc[8];
    #pragma unroll
    for (int i = 0; i < 8; i++) acc[i] = make_float4(0.f, 0.f, 0.f, 0.f);

    #pragma unroll 4
    for (int k = 0; k < GC; k++) {
        float4 w = ((const float4*)(sW + k * GC))[lane];
        #pragma unroll
        for (int i = 0; i < 8; i++) {
            float a = sRow[(r0 + i) * GC + k];   // warp-broadcast LDS
            acc[i].x += a * w.x;
            acc[i].y += a * w.y;
            acc[i].z += a * w.z;
            acc[i].w += a * w.w;
        }
    }

    float4 bv = ((const float4*)sBias)[lane];
    #pragma unroll
    for (int i = 0; i < 8; i++) {
        int grow = row_base + r0 + i;
        if (grow < total_rows) {
            float4 o;
            o.x = fmaxf(acc[i].x + bv.x, 0.f);
            o.y = fmaxf(acc[i].y + bv.y, 0.f);
            o.z = fmaxf(acc[i].z + bv.z, 0.f);
            o.w = fmaxf(acc[i].w + bv.w, 0.f);
            ((float4*)(out + (size_t)grow * GC))[lane] = o;
        }
    }
}

// ---------------------------------------------------------------------------
// Launch
// Inputs (metadata order): x [B,N,C], edge_row [E], edge_col [E],
//                          edge_vals [E], W [C,C], b [C]
// ---------------------------------------------------------------------------
extern "C" void kernel_launch(void* const* d_in, const int* in_sizes, int n_in,
                              void* d_out, int out_size) {
    const float* x     = (const float*)d_in[0];
    const int*   erow  = (const int*)d_in[1];
    const int*   ecol  = (const int*)d_in[2];
    const float* evals = (const float*)d_in[3];
    const float* W     = (const float*)d_in[4];
    const float* bias  = (const float*)d_in[5];
    float* out = (float*)d_out;

    int E = in_sizes[1];
    int N = in_sizes[0] / (GB * GC);
    int total_rows = out_size / GC;   // B*N

    // 1) zero scratch
    {
        size_t n_float4 = (size_t)GB * N * GC / 4;
        int threads = 256;
        int blocks = (int)((n_float4 + threads - 1) / threads);
        zero_agg_kernel<<<blocks, threads>>>(n_float4);
    }

    // 2) edge scatter
    {
        long long total = (long long)E * (GB * (GC / 4));
        int threads = 256;
        long long blocks = (total + threads - 1) / threads;
        scatter_kernel<<<(unsigned)blocks, threads>>>(x, erow, ecol, evals, E, N);
    }

    // 3) GEMM + bias + ReLU
    {
        static bool attr_set = false;
        size_t smem_bytes = (size_t)(GC * GC + ROWS_PER_BLOCK * GC + GC) * sizeof(float);
        if (!attr_set) {
            cudaFuncSetAttribute(gemm_bias_relu_kernel,
                                 cudaFuncAttributeMaxDynamicSharedMemorySize,
                                 (int)smem_bytes);
            attr_set = true;
        }
        int blocks = (total_rows + ROWS_PER_BLOCK - 1) / ROWS_PER_BLOCK;
        gemm_bias_relu_kernel<<<blocks, GEMM_THREADS, smem_bytes>>>(W, bias, out, total_rows);
    }
}

// round 2
// speedup vs baseline: 1.7798x; 1.7798x over previous
#include <cuda_runtime.h>
#include <cuda_bf16.h>
#include <cstdint>

// Problem constants (B=4, N=50000, E=800000, C_IN=C_OUT=128)
#define GB 4
#define GC 128
#define MAXN 50000

// Scratch: agg[b][n][c]  (4*50000*128 floats = 102.4 MB, static device alloc)
__device__ float g_agg[(size_t)GB * MAXN * GC];

// ---------------------------------------------------------------------------
// f32x2 packed-math helpers (Blackwell sm_103a; ptxas won't auto-fuse these)
// ---------------------------------------------------------------------------
__device__ __forceinline__ unsigned long long pack_f32x2(float lo, float hi) {
    unsigned long long r;
    asm("mov.b64 %0, {%1, %2};" : "=l"(r) : "f"(lo), "f"(hi));
    return r;
}
__device__ __forceinline__ void unpack_f32x2(unsigned long long v, float& lo, float& hi) {
    asm("mov.b64 {%0, %1}, %2;" : "=f"(lo), "=f"(hi) : "l"(v));
}
__device__ __forceinline__ void fma_f32x2(unsigned long long& d,
                                          unsigned long long a,
                                          unsigned long long b) {
    asm("fma.rn.f32x2 %0, %1, %2, %0;" : "+l"(d) : "l"(a), "l"(b));
}

// ---------------------------------------------------------------------------
// Kernel 1: edge scatter with vectorized reductions.
// One thread per (edge, batch, float4-chunk). 32 consecutive threads cover one
// (edge,batch) row of 128 floats -> coalesced 512B gather of x; edge metadata
// is warp-uniform (L1 broadcast). red.global.add.v4.f32 = 1 RED instr/thread.
// ---------------------------------------------------------------------------
__global__ void scatter_kernel(const float* __restrict__ x,
                               const int* __restrict__ erow,
                               const int* __restrict__ ecol,
                               const float* __restrict__ evals,
                               int E, int N) {
    long long idx = (long long)blockIdx.x * blockDim.x + threadIdx.x;
    long long total = (long long)E * (GB * (GC / 4));   // E * 4 * 32
    if (idx >= total) return;

    int chunk = (int)(idx & 31);          // which float4 of the 128-float row
    int b     = (int)((idx >> 5) & 3);    // batch
    int e     = (int)(idx >> 7);          // edge

    int r = erow[e];
    int c = ecol[e];
    float v = evals[e];

    const float4 xv = ((const float4*)(x + ((size_t)b * N + c) * GC))[chunk];
    float* dst = g_agg + ((size_t)b * N + r) * GC + (size_t)chunk * 4;

    asm volatile("red.global.add.v4.f32 [%0], {%1, %2, %3, %4};"
                 :: "l"(dst), "f"(v * xv.x), "f"(v * xv.y),
                    "f"(v * xv.z), "f"(v * xv.w)
                 : "memory");
}

// ---------------------------------------------------------------------------
// Kernel 2: fused dense GEMM (agg @ W) + bias + ReLU, packed f32x2 FFMA.
// Block = 256 threads (8 warps), 64 rows/block; each warp handles 8 rows,
// each thread 4 output columns (as 2 packed f32x2 accumulators per row).
// Dynamic smem: W (64KB) + 64 agg rows (32KB) + bias (512B).
// ---------------------------------------------------------------------------
#define ROWS_PER_BLOCK 64
#define GEMM_THREADS 256

__global__ void gemm_bias_relu_kernel(const float* __restrict__ W,
                                      const float* __restrict__ bias,
                                      float* __restrict__ out,
                                      int total_rows) {
    extern __shared__ float smem[];
    float* sW    = smem;                       // 128*128
    float* sRow  = smem + GC * GC;             // 64*128
    float* sBias = sRow + ROWS_PER_BLOCK * GC; // 128

    int tid = threadIdx.x;
    int warp = tid >> 5;
    int lane = tid & 31;

    // Cooperative load of W (16384 floats -> 16 float4 per thread)
    {
        const float4* Wv = (const float4*)W;
        float4* sWv = (float4*)sW;
        #pragma unroll
        for (int i = 0; i < (GC * GC / 4) / GEMM_THREADS; i++) {
            sWv[tid + i * GEMM_THREADS] = Wv[tid + i * GEMM_THREADS];
        }
        if (tid < GC) sBias[tid] = bias[tid];
    }

    int row_base = blockIdx.x * ROWS_PER_BLOCK;

    // Cooperative load of 64 agg rows (2048 float4)
    {
        const float4* Av = (const float4*)(g_agg + (size_t)row_base * GC);
        float4* sRv = (float4*)sRow;
        int nvec = ROWS_PER_BLOCK * GC / 4;  // 2048
        for (int i = tid; i < nvec; i += GEMM_THREADS) {
            int row = row_base + (i * 4) / GC;
            if (row < total_rows) sRv[i] = Av[i];
        }
    }
    __syncthreads();

    int r0 = warp * 8;  // local row offset within block

    // acc[i][0] = packed cols (4*lane, 4*lane+1), acc[i][1] = (4*lane+2, +3)
    unsigned long long acc[8][2];
    #pragma unroll
    for (int i = 0; i < 8; i++) { acc[i][0] = 0ull; acc[i][1] = 0ull; }

    #pragma unroll 4
    for (int k = 0; k < GC; k++) {
        // 16B of W row k for this lane's 4 columns, viewed as two f32x2 packs
        ulonglong2 w2 = ((const ulonglong2*)(sW + (size_t)k * GC))[lane];
        #pragma unroll
        for (int i = 0; i < 8; i++) {
            float a = sRow[(r0 + i) * GC + k];        // warp-broadcast LDS
            unsigned long long pa = pack_f32x2(a, a); // alu pipe, overlaps fma
            fma_f32x2(acc[i][0], pa, w2.x);
            fma_f32x2(acc[i][1], pa, w2.y);
        }
    }

    float4 bv = ((const float4*)sBias)[lane];
    #pragma unroll
    for (int i = 0; i < 8; i++) {
        int grow = row_base + r0 + i;
        if (grow < total_rows) {
            float4 o;
            unpack_f32x2(acc[i][0], o.x, o.y);
            unpack_f32x2(acc[i][1], o.z, o.w);
            o.x = fmaxf(o.x + bv.x, 0.f);
            o.y = fmaxf(o.y + bv.y, 0.f);
            o.z = fmaxf(o.z + bv.z, 0.f);
            o.w = fmaxf(o.w + bv.w, 0.f);
            ((float4*)(out + (size_t)grow * GC))[lane] = o;
        }
    }
}

// ---------------------------------------------------------------------------
// Launch
// Inputs (metadata order): x [B,N,C], edge_row [E], edge_col [E],
//                          edge_vals [E], W [C,C], b [C]
// ---------------------------------------------------------------------------
extern "C" void kernel_launch(void* const* d_in, const int* in_sizes, int n_in,
                              void* d_out, int out_size) {
    const float* x     = (const float*)d_in[0];
    const int*   erow  = (const int*)d_in[1];
    const int*   ecol  = (const int*)d_in[2];
    const float* evals = (const float*)d_in[3];
    const float* W     = (const float*)d_in[4];
    const float* bias  = (const float*)d_in[5];
    float* out = (float*)d_out;

    int E = in_sizes[1];
    int N = in_sizes[0] / (GB * GC);
    int total_rows = out_size / GC;   // B*N

    // 1) zero scratch via memset node (graph-capturable)
    {
        void* agg_ptr = nullptr;
        cudaGetSymbolAddress(&agg_ptr, g_agg);
        cudaMemsetAsync(agg_ptr, 0, (size_t)GB * N * GC * sizeof(float));
    }

    // 2) edge scatter (vectorized red)
    {
        long long total = (long long)E * (GB * (GC / 4));
        int threads = 256;
        long long blocks = (total + threads - 1) / threads;
        scatter_kernel<<<(unsigned)blocks, threads>>>(x, erow, ecol, evals, E, N);
    }

    // 3) GEMM + bias + ReLU
    {
        static bool attr_set = false;
        size_t smem_bytes = (size_t)(GC * GC + ROWS_PER_BLOCK * GC + GC) * sizeof(float);
        if (!attr_set) {
            cudaFuncSetAttribute(gemm_bias_relu_kernel,
                                 cudaFuncAttributeMaxDynamicSharedMemorySize,
                                 (int)smem_bytes);
            attr_set = true;
        }
        int blocks = (total_rows + ROWS_PER_BLOCK - 1) / ROWS_PER_BLOCK;
        gemm_bias_relu_kernel<<<blocks, GEMM_THREADS, smem_bytes>>>(W, bias, out, total_rows);
    }
}

// round 3
// speedup vs baseline: 2.9055x; 1.6325x over previous
#include <cuda_runtime.h>
#include <cuda_bf16.h>
#include <cstdint>

// Problem constants (B=4, N=50000, E=800000, C_IN=C_OUT=128)
#define GB 4
#define GC 128
#define MAXN 50000
#define MAXE 800000

// y = x @ W scratch (102.4 MB)
__device__ float g_y[(size_t)GB * MAXN * GC];
// CSR structures
__device__ int g_cnt[MAXN];          // row histogram / reused
__device__ int g_rowptr[MAXN + 1];   // exclusive prefix
__device__ int g_cursor[MAXN];       // fill cursors
__device__ unsigned long long g_csr[MAXE];  // packed (col | val<<32), row-sorted

// ---------------------------------------------------------------------------
// f32x2 packed-math helpers (Blackwell sm_103a)
// ---------------------------------------------------------------------------
__device__ __forceinline__ unsigned long long pack_f32x2(float lo, float hi) {
    unsigned long long r;
    asm("mov.b64 %0, {%1, %2};" : "=l"(r) : "f"(lo), "f"(hi));
    return r;
}
__device__ __forceinline__ void unpack_f32x2(unsigned long long v, float& lo, float& hi) {
    asm("mov.b64 {%0, %1}, %2;" : "=f"(lo), "=f"(hi) : "l"(v));
}
__device__ __forceinline__ void fma_f32x2(unsigned long long& d,
                                          unsigned long long a,
                                          unsigned long long b) {
    asm("fma.rn.f32x2 %0, %1, %2, %0;" : "+l"(d) : "l"(a), "l"(b));
}

// ---------------------------------------------------------------------------
// CSR build kernel 1: histogram of edge rows
// ---------------------------------------------------------------------------
__global__ void hist_kernel(const int* __restrict__ erow, int E) {
    int e = blockIdx.x * blockDim.x + threadIdx.x;
    if (e < E) atomicAdd(&g_cnt[erow[e]], 1);
}

// ---------------------------------------------------------------------------
// CSR build kernel 2: single-block exclusive scan of counts -> rowptr
// ---------------------------------------------------------------------------
__global__ void scan_kernel(int N) {
    __shared__ int s[1024];
    __shared__ int carry;
    int t = threadIdx.x;
    if (t == 0) { carry = 0; g_rowptr[0] = 0; }
    __syncthreads();

    for (int base = 0; base < N; base += 1024) {
        int v = (base + t < N) ? g_cnt[base + t] : 0;
        s[t] = v;
        __syncthreads();
        // Hillis-Steele inclusive scan
        #pragma unroll
        for (int off = 1; off < 1024; off <<= 1) {
            int u = (t >= off) ? s[t - off] : 0;
            __syncthreads();
            s[t] += u;
            __syncthreads();
        }
        int c = carry;
        if (base + t < N) g_rowptr[base + t + 1] = c + s[t];
        __syncthreads();
        if (t == 1023) carry = c + s[1023];
        __syncthreads();
    }
}

// ---------------------------------------------------------------------------
// CSR build kernel 3: fill sorted (col,val) pairs
// ---------------------------------------------------------------------------
__global__ void fill_kernel(const int* __restrict__ erow,
                            const int* __restrict__ ecol,
                            const float* __restrict__ evals,
                            int E) {
    int e = blockIdx.x * blockDim.x + threadIdx.x;
    if (e < E) {
        int r = erow[e];
        int pos = atomicAdd(&g_cursor[r], 1);
        unsigned long long m = (unsigned long long)(unsigned)ecol[e]
                             | ((unsigned long long)__float_as_uint(evals[e]) << 32);
        g_csr[pos] = m;
    }
}

// ---------------------------------------------------------------------------
// GEMM kernel: y = x @ W  (no bias/relu; those fuse into the gather)
// 256 threads, 64 rows/block, FFMA2 packed math, W + row tile in smem.
// ---------------------------------------------------------------------------
#define ROWS_PER_BLOCK 64
#define GEMM_THREADS 256

__global__ void gemm_kernel(const float* __restrict__ x,
                            const float* __restrict__ W,
                            int total_rows) {
    extern __shared__ float smem[];
    float* sW   = smem;                       // 128*128
    float* sRow = smem + GC * GC;             // 64*128

    int tid = threadIdx.x;
    int warp = tid >> 5;
    int lane = tid & 31;

    {
        const float4* Wv = (const float4*)W;
        float4* sWv = (float4*)sW;
        #pragma unroll
        for (int i = 0; i < (GC * GC / 4) / GEMM_THREADS; i++)
            sWv[tid + i * GEMM_THREADS] = Wv[tid + i * GEMM_THREADS];
    }

    int row_base = blockIdx.x * ROWS_PER_BLOCK;
    {
        const float4* Av = (const float4*)(x + (size_t)row_base * GC);
        float4* sRv = (float4*)sRow;
        int nvec = ROWS_PER_BLOCK * GC / 4;
        for (int i = tid; i < nvec; i += GEMM_THREADS) {
            int row = row_base + (i * 4) / GC;
            if (row < total_rows) sRv[i] = Av[i];
        }
    }
    __syncthreads();

    int r0 = warp * 8;

    unsigned long long acc[8][2];
    #pragma unroll
    for (int i = 0; i < 8; i++) { acc[i][0] = 0ull; acc[i][1] = 0ull; }

    #pragma unroll 4
    for (int k = 0; k < GC; k++) {
        ulonglong2 w2 = ((const ulonglong2*)(sW + (size_t)k * GC))[lane];
        #pragma unroll
        for (int i = 0; i < 8; i++) {
            float a = sRow[(r0 + i) * GC + k];
            unsigned long long pa = pack_f32x2(a, a);
            fma_f32x2(acc[i][0], pa, w2.x);
            fma_f32x2(acc[i][1], pa, w2.y);
        }
    }

    #pragma unroll
    for (int i = 0; i < 8; i++) {
        int grow = row_base + r0 + i;
        if (grow < total_rows) {
            float4 o;
            unpack_f32x2(acc[i][0], o.x, o.y);
            unpack_f32x2(acc[i][1], o.z, o.w);
            ((float4*)(g_y + (size_t)grow * GC))[lane] = o;
        }
    }
}

// ---------------------------------------------------------------------------
// Gather kernel: out[b,r,:] = relu( sum_e val_e * y[b,col_e,:] + bias )
// One warp per node row r; all 4 batches handled simultaneously
// (metadata amortized 4x, 4 independent 512B loads in flight per edge).
// ---------------------------------------------------------------------------
__global__ void gather_kernel(const float* __restrict__ bias,
                              float* __restrict__ out,
                              int N) {
    int warp_global = (blockIdx.x * blockDim.x + threadIdx.x) >> 5;
    int lane = threadIdx.x & 31;
    if (warp_global >= N) return;
    int r = warp_global;

    float4 bv = ((const float4*)bias)[lane];

    int start = g_rowptr[r];
    int end   = g_rowptr[r + 1];

    float4 a0 = make_float4(0.f, 0.f, 0.f, 0.f);
    float4 a1 = a0, a2 = a0, a3 = a0;

    const size_t bstride = (size_t)N * GC;

    for (int e = start; e < end; e++) {
        unsigned long long m = g_csr[e];              // warp-uniform
        int col = (int)(m & 0xffffffffu);
        float v = __uint_as_float((unsigned)(m >> 32));

        const float* yc = g_y + (size_t)col * GC;
        float4 y0 = ((const float4*)(yc              ))[lane];
        float4 y1 = ((const float4*)(yc + bstride    ))[lane];
        float4 y2 = ((const float4*)(yc + 2 * bstride))[lane];
        float4 y3 = ((const float4*)(yc + 3 * bstride))[lane];

        a0.x += v * y0.x; a0.y += v * y0.y; a0.z += v * y0.z; a0.w += v * y0.w;
        a1.x += v * y1.x; a1.y += v * y1.y; a1.z += v * y1.z; a1.w += v * y1.w;
        a2.x += v * y2.x; a2.y += v * y2.y; a2.z += v * y2.z; a2.w += v * y2.w;
        a3.x += v * y3.x; a3.y += v * y3.y; a3.z += v * y3.z; a3.w += v * y3.w;
    }

    float4 o;
    float* dst = out + (size_t)r * GC;
    o.x = fmaxf(a0.x + bv.x, 0.f); o.y = fmaxf(a0.y + bv.y, 0.f);
    o.z = fmaxf(a0.z + bv.z, 0.f); o.w = fmaxf(a0.w + bv.w, 0.f);
    ((float4*)(dst))[lane] = o;
    o.x = fmaxf(a1.x + bv.x, 0.f); o.y = fmaxf(a1.y + bv.y, 0.f);
    o.z = fmaxf(a1.z + bv.z, 0.f); o.w = fmaxf(a1.w + bv.w, 0.f);
    ((float4*)(dst + bstride))[lane] = o;
    o.x = fmaxf(a2.x + bv.x, 0.f); o.y = fmaxf(a2.y + bv.y, 0.f);
    o.z = fmaxf(a2.z + bv.z, 0.f); o.w = fmaxf(a2.w + bv.w, 0.f);
    ((float4*)(dst + 2 * bstride))[lane] = o;
    o.x = fmaxf(a3.x + bv.x, 0.f); o.y = fmaxf(a3.y + bv.y, 0.f);
    o.z = fmaxf(a3.z + bv.z, 0.f); o.w = fmaxf(a3.w + bv.w, 0.f);
    ((float4*)(dst + 3 * bstride))[lane] = o;
}

// ---------------------------------------------------------------------------
// Launch
// Inputs: x [B,N,C], edge_row [E], edge_col [E], edge_vals [E], W [C,C], b [C]
// ---------------------------------------------------------------------------
extern "C" void kernel_launch(void* const* d_in, const int* in_sizes, int n_in,
                              void* d_out, int out_size) {
    const float* x     = (const float*)d_in[0];
    const int*   erow  = (const int*)d_in[1];
    const int*   ecol  = (const int*)d_in[2];
    const float* evals = (const float*)d_in[3];
    const float* W     = (const float*)d_in[4];
    const float* bias  = (const float*)d_in[5];
    float* out = (float*)d_out;

    int E = in_sizes[1];
    int N = in_sizes[0] / (GB * GC);
    int total_rows = out_size / GC;   // B*N

    void *cnt_ptr = nullptr, *rowptr_ptr = nullptr, *cursor_ptr = nullptr;
    cudaGetSymbolAddress(&cnt_ptr, g_cnt);
    cudaGetSymbolAddress(&rowptr_ptr, g_rowptr);
    cudaGetSymbolAddress(&cursor_ptr, g_cursor);

    // --- CSR build ---
    cudaMemsetAsync(cnt_ptr, 0, (size_t)N * sizeof(int));
    hist_kernel<<<(E + 255) / 256, 256>>>(erow, E);
    scan_kernel<<<1, 1024>>>(N);
    cudaMemcpyAsync(cursor_ptr, rowptr_ptr, (size_t)N * sizeof(int),
                    cudaMemcpyDeviceToDevice);
    fill_kernel<<<(E + 255) / 256, 256>>>(erow, ecol, evals, E);

    // --- y = x @ W ---
    {
        static bool attr_set = false;
        size_t smem_bytes = (size_t)(GC * GC + ROWS_PER_BLOCK * GC) * sizeof(float);
        if (!attr_set) {
            cudaFuncSetAttribute(gemm_kernel,
                                 cudaFuncAttributeMaxDynamicSharedMemorySize,
                                 (int)smem_bytes);
            attr_set = true;
        }
        int blocks = (total_rows + ROWS_PER_BLOCK - 1) / ROWS_PER_BLOCK;
        gemm_kernel<<<blocks, GEMM_THREADS, smem_bytes>>>(x, W, total_rows);
    }

    // --- out = relu(A . y + bias) ---
    {
        int threads = 256;                 // 8 warps/block, 1 warp per row
        int blocks = (N + 7) / 8;
        gather_kernel<<<blocks, threads>>>(bias, out, N);
    }
}

// round 4
// speedup vs baseline: 3.1810x; 1.0948x over previous
#include <cuda_runtime.h>
#include <cuda_bf16.h>
#include <cstdint>

// Problem constants (B=4, N=50000, E=800000, C_IN=C_OUT=128)
#define GB 4
#define GC 128
#define MAXN 50000
#define MAXE 800000

// y = x @ W scratch (102.4 MB)
__device__ float g_y[(size_t)GB * MAXN * GC];
// CSR structures
__device__ int g_cnt[MAXN];
__device__ int g_rowptr[MAXN + 1];
__device__ int g_cursor[MAXN];
__device__ unsigned long long g_csr[MAXE];  // packed (col | val<<32), row-grouped

// ---------------------------------------------------------------------------
// f32x2 packed-math helpers (Blackwell sm_103a)
// ---------------------------------------------------------------------------
__device__ __forceinline__ unsigned long long pack_f32x2(float lo, float hi) {
    unsigned long long r;
    asm("mov.b64 %0, {%1, %2};" : "=l"(r) : "f"(lo), "f"(hi));
    return r;
}
__device__ __forceinline__ void unpack_f32x2(unsigned long long v, float& lo, float& hi) {
    asm("mov.b64 {%0, %1}, %2;" : "=f"(lo), "=f"(hi) : "l"(v));
}
__device__ __forceinline__ void fma_f32x2(unsigned long long& d,
                                          unsigned long long a,
                                          unsigned long long b) {
    asm("fma.rn.f32x2 %0, %1, %2, %0;" : "+l"(d) : "l"(a), "l"(b));
}

// ---------------------------------------------------------------------------
// CSR build 1: histogram of edge rows
// ---------------------------------------------------------------------------
__global__ void hist_kernel(const int* __restrict__ erow, int E) {
    int e = blockIdx.x * blockDim.x + threadIdx.x;
    if (e < E) atomicAdd(&g_cnt[erow[e]], 1);
}

// ---------------------------------------------------------------------------
// CSR build 2: single-block warp-shuffle exclusive scan -> rowptr + cursor
// ---------------------------------------------------------------------------
__global__ void scan_kernel(int N) {
    __shared__ int wsum[32];
    __shared__ int carry;
    int t = threadIdx.x, lane = t & 31, w = t >> 5;
    if (t == 0) { carry = 0; g_rowptr[0] = 0; }
    __syncthreads();

    for (int base = 0; base < N; base += 1024) {
        int i = base + t;
        int v = (i < N) ? g_cnt[i] : 0;
        int s = v;
        #pragma unroll
        for (int off = 1; off < 32; off <<= 1) {
            int u = __shfl_up_sync(0xffffffffu, s, off);
            if (lane >= off) s += u;
        }
        if (lane == 31) wsum[w] = s;
        __syncthreads();
        if (w == 0) {
            int ws = wsum[lane];
            #pragma unroll
            for (int off = 1; off < 32; off <<= 1) {
                int u = __shfl_up_sync(0xffffffffu, ws, off);
                if (lane >= off) ws += u;
            }
            wsum[lane] = ws;
        }
        __syncthreads();
        int prefix = carry + (w ? wsum[w - 1] : 0);
        int incl = prefix + s;
        if (i < N) {
            g_rowptr[i + 1] = incl;
            g_cursor[i] = incl - v;   // exclusive prefix = fill cursor start
        }
        __syncthreads();
        if (t == 1023) carry = incl;
        __syncthreads();
    }
}

// ---------------------------------------------------------------------------
// CSR build 3: fill (col,val) pairs grouped by row
// ---------------------------------------------------------------------------
__global__ void fill_kernel(const int* __restrict__ erow,
                            const int* __restrict__ ecol,
                            const float* __restrict__ evals,
                            int E) {
    int e = blockIdx.x * blockDim.x + threadIdx.x;
    if (e < E) {
        int r = erow[e];
        int pos = atomicAdd(&g_cursor[r], 1);
        unsigned long long m = (unsigned long long)(unsigned)ecol[e]
                             | ((unsigned long long)__float_as_uint(evals[e]) << 32);
        g_csr[pos] = m;
    }
}

// ---------------------------------------------------------------------------
// GEMM kernel: y = x @ W.  256 threads, 64 rows/block.
// A-tile staged pair-major transposed: sP[row/2][k][2] so a row-pair at
// column k is one LDS.64 broadcast (natural f32x2 operand, no dup-a packs).
// W duplicated into f32x2 (4 packs/k).  16 FFMA2/warp/k.
// ---------------------------------------------------------------------------
#define ROWS_PER_BLOCK 64
#define GEMM_THREADS 256

__global__ void __launch_bounds__(GEMM_THREADS, 2)
gemm_kernel(const float* __restrict__ x,
            const float* __restrict__ W,
            int total_rows) {
    extern __shared__ float smem[];
    float* sW = smem;                 // 128*128 = 64KB
    float* sP = smem + GC * GC;       // pair-major A tile: [32][128][2] = 32KB

    int tid = threadIdx.x;
    int warp = tid >> 5;
    int lane = tid & 31;

    // Load W
    {
        const float4* Wv = (const float4*)W;
        float4* sWv = (float4*)sW;
        #pragma unroll
        for (int i = 0; i < (GC * GC / 4) / GEMM_THREADS; i++)
            sWv[tid + i * GEMM_THREADS] = Wv[tid + i * GEMM_THREADS];
    }

    // Load + transpose A tile into pair-major layout
    int row_base = blockIdx.x * ROWS_PER_BLOCK;
    {
        const float4* Av = (const float4*)(x + (size_t)row_base * GC);
        int nvec = ROWS_PER_BLOCK * GC / 4;  // 2048
        for (int i = tid; i < nvec; i += GEMM_THREADS) {
            int row = i >> 5;          // 32 float4 per row
            int c4  = i & 31;
            float4 v = (row_base + row < total_rows) ? Av[i]
                                                     : make_float4(0.f, 0.f, 0.f, 0.f);
            int k0 = c4 * 4;
            int base = ((row >> 1) * GC) * 2 + (row & 1);  // sP[(row/2)][k][row&1]
            sP[base + (k0 + 0) * 2] = v.x;
            sP[base + (k0 + 1) * 2] = v.y;
            sP[base + (k0 + 2) * 2] = v.z;
            sP[base + (k0 + 3) * 2] = v.w;
        }
    }
    __syncthreads();

    int p0 = warp * 4;  // 4 row-pairs (8 rows) per warp
    const float2* sP2 = (const float2*)sP;   // index: pair*128 + k

    unsigned long long acc[4][4];
    #pragma unroll
    for (int p = 0; p < 4; p++)
        #pragma unroll
        for (int j = 0; j < 4; j++) acc[p][j] = 0ull;

    #pragma unroll 4
    for (int k = 0; k < GC; k++) {
        float4 w = ((const float4*)(sW + (size_t)k * GC))[lane];
        unsigned long long wd0 = pack_f32x2(w.x, w.x);
        unsigned long long wd1 = pack_f32x2(w.y, w.y);
        unsigned long long wd2 = pack_f32x2(w.z, w.z);
        unsigned long long wd3 = pack_f32x2(w.w, w.w);

        float2 a0 = sP2[(p0 + 0) * GC + k];   // rows 2p0,   2p0+1
        float2 a1 = sP2[(p0 + 1) * GC + k];
        float2 a2 = sP2[(p0 + 2) * GC + k];
        float2 a3 = sP2[(p0 + 3) * GC + k];
        unsigned long long ap0 = pack_f32x2(a0.x, a0.y);
        unsigned long long ap1 = pack_f32x2(a1.x, a1.y);
        unsigned long long ap2 = pack_f32x2(a2.x, a2.y);
        unsigned long long ap3 = pack_f32x2(a3.x, a3.y);

        fma_f32x2(acc[0][0], ap0, wd0); fma_f32x2(acc[0][1], ap0, wd1);
        fma_f32x2(acc[0][2], ap0, wd2); fma_f32x2(acc[0][3], ap0, wd3);
        fma_f32x2(acc[1][0], ap1, wd0); fma_f32x2(acc[1][1], ap1, wd1);
        fma_f32x2(acc[1][2], ap1, wd2); fma_f32x2(acc[1][3], ap1, wd3);
        fma_f32x2(acc[2][0], ap2, wd0); fma_f32x2(acc[2][1], ap2, wd1);
        fma_f32x2(acc[2][2], ap2, wd2); fma_f32x2(acc[2][3], ap2, wd3);
        fma_f32x2(acc[3][0], ap3, wd0); fma_f32x2(acc[3][1], ap3, wd1);
        fma_f32x2(acc[3][2], ap3, wd2); fma_f32x2(acc[3][3], ap3, wd3);
    }

    // Epilogue: acc[p][j] holds (row 2p, row 2p+1) for column 4*lane+j
    #pragma unroll
    for (int p = 0; p < 4; p++) {
        float4 lo4, hi4;
        unpack_f32x2(acc[p][0], lo4.x, hi4.x);
        unpack_f32x2(acc[p][1], lo4.y, hi4.y);
        unpack_f32x2(acc[p][2], lo4.z, hi4.z);
        unpack_f32x2(acc[p][3], lo4.w, hi4.w);
        int grow0 = row_base + (p0 + p) * 2;
        if (grow0 < total_rows)
            ((float4*)(g_y + (size_t)grow0 * GC))[lane] = lo4;
        if (grow0 + 1 < total_rows)
            ((float4*)(g_y + (size_t)(grow0 + 1) * GC))[lane] = hi4;
    }
}

// ---------------------------------------------------------------------------
// Gather kernel: out[b,r,:] = relu( sum_e val_e * y[b,col_e,:] + bias )
// One warp per node row r; 4 batches per warp.
// ---------------------------------------------------------------------------
__global__ void gather_kernel(const float* __restrict__ bias,
                              float* __restrict__ out,
                              int N) {
    int warp_global = (blockIdx.x * blockDim.x + threadIdx.x) >> 5;
    int lane = threadIdx.x & 31;
    if (warp_global >= N) return;
    int r = warp_global;

    float4 bv = ((const float4*)bias)[lane];

    int start = g_rowptr[r];
    int end   = g_rowptr[r + 1];

    float4 a0 = make_float4(0.f, 0.f, 0.f, 0.f);
    float4 a1 = a0, a2 = a0, a3 = a0;

    const size_t bstride = (size_t)N * GC;

    for (int e = start; e < end; e++) {
        unsigned long long m = g_csr[e];
        int col = (int)(m & 0xffffffffu);
        float v = __uint_as_float((unsigned)(m >> 32));

        const float* yc = g_y + (size_t)col * GC;
        float4 y0 = ((const float4*)(yc              ))[lane];
        float4 y1 = ((const float4*)(yc + bstride    ))[lane];
        float4 y2 = ((const float4*)(yc + 2 * bstride))[lane];
        float4 y3 = ((const float4*)(yc + 3 * bstride))[lane];

        a0.x += v * y0.x; a0.y += v * y0.y; a0.z += v * y0.z; a0.w += v * y0.w;
        a1.x += v * y1.x; a1.y += v * y1.y; a1.z += v * y1.z; a1.w += v * y1.w;
        a2.x += v * y2.x; a2.y += v * y2.y; a2.z += v * y2.z; a2.w += v * y2.w;
        a3.x += v * y3.x; a3.y += v * y3.y; a3.z += v * y3.z; a3.w += v * y3.w;
    }

    float4 o;
    float* dst = out + (size_t)r * GC;
    o.x = fmaxf(a0.x + bv.x, 0.f); o.y = fmaxf(a0.y + bv.y, 0.f);
    o.z = fmaxf(a0.z + bv.z, 0.f); o.w = fmaxf(a0.w + bv.w, 0.f);
    ((float4*)(dst))[lane] = o;
    o.x = fmaxf(a1.x + bv.x, 0.f); o.y = fmaxf(a1.y + bv.y, 0.f);
    o.z = fmaxf(a1.z + bv.z, 0.f); o.w = fmaxf(a1.w + bv.w, 0.f);
    ((float4*)(dst + bstride))[lane] = o;
    o.x = fmaxf(a2.x + bv.x, 0.f); o.y = fmaxf(a2.y + bv.y, 0.f);
    o.z = fmaxf(a2.z + bv.z, 0.f); o.w = fmaxf(a2.w + bv.w, 0.f);
    ((float4*)(dst + 2 * bstride))[lane] = o;
    o.x = fmaxf(a3.x + bv.x, 0.f); o.y = fmaxf(a3.y + bv.y, 0.f);
    o.z = fmaxf(a3.z + bv.z, 0.f); o.w = fmaxf(a3.w + bv.w, 0.f);
    ((float4*)(dst + 3 * bstride))[lane] = o;
}

// ---------------------------------------------------------------------------
// Launch. CSR build forked to a side stream, overlapped with the GEMM.
// Inputs: x [B,N,C], edge_row [E], edge_col [E], edge_vals [E], W [C,C], b [C]
// ---------------------------------------------------------------------------
extern "C" void kernel_launch(void* const* d_in, const int* in_sizes, int n_in,
                              void* d_out, int out_size) {
    const float* x     = (const float*)d_in[0];
    const int*   erow  = (const int*)d_in[1];
    const int*   ecol  = (const int*)d_in[2];
    const float* evals = (const float*)d_in[3];
    const float* W     = (const float*)d_in[4];
    const float* bias  = (const float*)d_in[5];
    float* out = (float*)d_out;

    int E = in_sizes[1];
    int N = in_sizes[0] / (GB * GC);
    int total_rows = out_size / GC;   // B*N

    static cudaStream_t s_side = nullptr;
    static cudaEvent_t ev_fork = nullptr, ev_join = nullptr;
    if (s_side == nullptr) {
        cudaStreamCreateWithFlags(&s_side, cudaStreamNonBlocking);
        cudaEventCreateWithFlags(&ev_fork, cudaEventDisableTiming);
        cudaEventCreateWithFlags(&ev_join, cudaEventDisableTiming);
        size_t smem_bytes = (size_t)(GC * GC + ROWS_PER_BLOCK * GC) * sizeof(float);
        cudaFuncSetAttribute(gemm_kernel,
                             cudaFuncAttributeMaxDynamicSharedMemorySize,
                             (int)smem_bytes);
    }

    void* cnt_ptr = nullptr;
    cudaGetSymbolAddress(&cnt_ptr, g_cnt);

    // --- fork: CSR build on side stream ---
    cudaEventRecord(ev_fork, 0);
    cudaStreamWaitEvent(s_side, ev_fork, 0);
    cudaMemsetAsync(cnt_ptr, 0, (size_t)N * sizeof(int), s_side);
    hist_kernel<<<(E + 255) / 256, 256, 0, s_side>>>(erow, E);
    scan_kernel<<<1, 1024, 0, s_side>>>(N);
    fill_kernel<<<(E + 255) / 256, 256, 0, s_side>>>(erow, ecol, evals, E);
    cudaEventRecord(ev_join, s_side);

    // --- main stream: y = x @ W ---
    {
        size_t smem_bytes = (size_t)(GC * GC + ROWS_PER_BLOCK * GC) * sizeof(float);
        int blocks = (total_rows + ROWS_PER_BLOCK - 1) / ROWS_PER_BLOCK;
        gemm_kernel<<<blocks, GEMM_THREADS, smem_bytes>>>(x, W, total_rows);
    }

    // --- join, then gather ---
    cudaStreamWaitEvent(0, ev_join, 0);
    {
        int threads = 256;                 // 8 warps/block, 1 warp per row
        int blocks = (N + 7) / 8;
        gather_kernel<<<blocks, threads>>>(bias, out, N);
    }
}

// round 6
// speedup vs baseline: 4.1741x; 1.3122x over previous
#include <cuda_runtime.h>
#include <cuda_bf16.h>
#include <cstdint>

// Problem constants (B=4, N=50000, E=800000, C_IN=C_OUT=128)
#define GB 4
#define GC 128
#define MAXN 50000
#define MAXE 800000
#define TILE_M 128
#define APAD 136   // padded row length (bf16 elems): 272B stride, conflict-free ldmatrix

// y = x @ W scratch (102.4 MB)
__device__ float g_y[(size_t)GB * MAXN * GC];
// CSR structures
__device__ int g_cnt[MAXN];
__device__ int g_rowptr[MAXN + 1];
__device__ int g_cursor[MAXN];
__device__ unsigned long long g_csr[MAXE];
// Pre-transposed, hi/lo-split W images: [n][k] bf16, padded to APAD
__device__ __align__(16) __nv_bfloat16 g_Whi[GC * APAD];
__device__ __align__(16) __nv_bfloat16 g_Wlo[GC * APAD];

// ---------------------------------------------------------------------------
// PTX helpers (base sm_103 target — no 'a' features)
// ---------------------------------------------------------------------------
__device__ __forceinline__ uint32_t smem_u32(const void* p) {
    uint32_t a;
    asm("{ .reg .u64 t; cvta.to.shared.u64 t, %1; cvt.u32.u64 %0, t; }"
        : "=r"(a) : "l"(p));
    return a;
}
__device__ __forceinline__ void ldsm4(uint32_t* r, uint32_t addr) {
    asm volatile("ldmatrix.sync.aligned.m8n8.x4.shared.b16 {%0,%1,%2,%3}, [%4];"
                 : "=r"(r[0]), "=r"(r[1]), "=r"(r[2]), "=r"(r[3]) : "r"(addr));
}
__device__ __forceinline__ void mma16816(float* d, const uint32_t* a, const uint32_t* b) {
    asm volatile("mma.sync.aligned.m16n8k16.row.col.f32.bf16.bf16.f32 "
                 "{%0,%1,%2,%3}, {%4,%5,%6,%7}, {%8,%9}, {%0,%1,%2,%3};"
                 : "+f"(d[0]), "+f"(d[1]), "+f"(d[2]), "+f"(d[3])
                 : "r"(a[0]), "r"(a[1]), "r"(a[2]), "r"(a[3]),
                   "r"(b[0]), "r"(b[1]));
}

// ---------------------------------------------------------------------------
// W prep: B[n][k] = W[k][n], split into bf16 hi + lo residual, padded rows.
// ---------------------------------------------------------------------------
__global__ void wprep_kernel(const float* __restrict__ W) {
    int idx = blockIdx.x * blockDim.x + threadIdx.x;
    if (idx >= GC * GC) return;
    int n = idx >> 7, k = idx & 127;
    float v = W[k * GC + n];
    __nv_bfloat16 h = __float2bfloat16(v);
    __nv_bfloat16 l = __float2bfloat16(v - __bfloat162float(h));
    g_Whi[n * APAD + k] = h;
    g_Wlo[n * APAD + k] = l;
}

// ---------------------------------------------------------------------------
// HMMA GEMM: y = x @ W via 3-pass bf16 split (hi*hi + lo*hi + hi*lo).
// 256 threads, tile 128x128x128. Warp w: rows w*16..w*16+15, all 128 cols.
// ---------------------------------------------------------------------------
__global__ void __launch_bounds__(256, 1)
gemm_hmma_kernel(const float* __restrict__ x, int total_rows) {
    extern __shared__ __nv_bfloat16 sm[];
    __nv_bfloat16* sAhi = sm;                  // 128 * APAD
    __nv_bfloat16* sAlo = sm + GC * APAD;
    __nv_bfloat16* sBhi = sm + 2 * GC * APAD;
    __nv_bfloat16* sBlo = sm + 3 * GC * APAD;

    int tid = threadIdx.x, wid = tid >> 5, lane = tid & 31;
    int row_base = blockIdx.x * TILE_M;

    // Copy pre-split W images (each 128*136*2 = 34816 B = 2176 uint4)
    {
        const uint4* sh = (const uint4*)g_Whi;
        const uint4* sl = (const uint4*)g_Wlo;
        uint4* dh = (uint4*)sBhi;
        uint4* dl = (uint4*)sBlo;
        for (int i = tid; i < (GC * APAD * 2) / 16; i += 256) {
            dh[i] = sh[i];
            dl[i] = sl[i];
        }
    }

    // Load A tile (128 x 128 f32), convert to bf16 hi/lo
    {
        const float4* src = (const float4*)(x + (size_t)row_base * GC);
        #pragma unroll
        for (int j = 0; j < 16; j++) {
            int i = tid + j * 256;
            int row = i >> 5, c4 = i & 31;
            float4 v = make_float4(0.f, 0.f, 0.f, 0.f);
            if (row_base + row < total_rows) v = src[i];
            __nv_bfloat16 h0 = __float2bfloat16(v.x), h1 = __float2bfloat16(v.y);
            __nv_bfloat16 h2 = __float2bfloat16(v.z), h3 = __float2bfloat16(v.w);
            __nv_bfloat16 l0 = __float2bfloat16(v.x - __bfloat162float(h0));
            __nv_bfloat16 l1 = __float2bfloat16(v.y - __bfloat162float(h1));
            __nv_bfloat16 l2 = __float2bfloat16(v.z - __bfloat162float(h2));
            __nv_bfloat16 l3 = __float2bfloat16(v.w - __bfloat162float(h3));
            int off = row * APAD + c4 * 4;
            uint32_t hh0 = (uint32_t)__bfloat16_as_ushort(h0) | ((uint32_t)__bfloat16_as_ushort(h1) << 16);
            uint32_t hh1 = (uint32_t)__bfloat16_as_ushort(h2) | ((uint32_t)__bfloat16_as_ushort(h3) << 16);
            uint32_t ll0 = (uint32_t)__bfloat16_as_ushort(l0) | ((uint32_t)__bfloat16_as_ushort(l1) << 16);
            uint32_t ll1 = (uint32_t)__bfloat16_as_ushort(l2) | ((uint32_t)__bfloat16_as_ushort(l3) << 16);
            *(uint2*)(sAhi + off) = make_uint2(hh0, hh1);
            *(uint2*)(sAlo + off) = make_uint2(ll0, ll1);
        }
    }
    __syncthreads();

    int r0 = wid * 16;

    // Per-lane ldmatrix base addresses (bytes)
    // A (m16k16, x4): lane -> row (lane&15), col-half (lane>>4)*8
    uint32_t aRowOff = ((uint32_t)(r0 + (lane & 15)) * APAD + (uint32_t)(lane >> 4) * 8) * 2;
    uint32_t aHiBase = smem_u32(sAhi) + aRowOff;
    uint32_t aLoBase = smem_u32(sAlo) + aRowOff;
    // B (two n8k16 tiles per x4): lane -> n row (lane&7)+((lane>>4)<<3), k-half ((lane>>3)&1)*8
    uint32_t bRowOff = ((uint32_t)((lane & 7) + ((lane >> 4) << 3)) * APAD
                        + (uint32_t)((lane >> 3) & 1) * 8) * 2;
    uint32_t bHi0 = smem_u32(sBhi) + bRowOff;
    uint32_t bLo0 = smem_u32(sBlo) + bRowOff;

    float acc[16][4];
    #pragma unroll
    for (int t = 0; t < 16; t++)
        #pragma unroll
        for (int j = 0; j < 4; j++) acc[t][j] = 0.f;

    #pragma unroll
    for (int ks = 0; ks < 8; ks++) {
        uint32_t ahi[4], alo[4];
        ldsm4(ahi, aHiBase + ks * 32);
        ldsm4(alo, aLoBase + ks * 32);
        #pragma unroll
        for (int nt2 = 0; nt2 < 8; nt2++) {
            uint32_t bhi[4], blo[4];
            uint32_t boff = (uint32_t)(nt2 * 16) * APAD * 2 + ks * 32;
            ldsm4(bhi, bHi0 + boff);
            ldsm4(blo, bLo0 + boff);
            mma16816(acc[nt2 * 2],     ahi, bhi);
            mma16816(acc[nt2 * 2 + 1], ahi, bhi + 2);
            mma16816(acc[nt2 * 2],     alo, bhi);
            mma16816(acc[nt2 * 2 + 1], alo, bhi + 2);
            mma16816(acc[nt2 * 2],     ahi, blo);
            mma16816(acc[nt2 * 2 + 1], ahi, blo + 2);
        }
    }

    // Epilogue: d0,d1 -> row r0+lane/4,   cols nt*8+(lane%4)*2 (+1)
    //           d2,d3 -> row r0+lane/4+8, same cols
    {
        int rlo = r0 + (lane >> 2);
        int col = (lane & 3) * 2;
        long g0 = (long)row_base + rlo;
        long g1 = g0 + 8;
        float* y0 = g_y + (size_t)g0 * GC + col;
        float* y1 = g_y + (size_t)g1 * GC + col;
        bool ok0 = g0 < total_rows, ok1 = g1 < total_rows;
        #pragma unroll
        for (int nt = 0; nt < 16; nt++) {
            if (ok0) *(float2*)(y0 + nt * 8) = make_float2(acc[nt][0], acc[nt][1]);
            if (ok1) *(float2*)(y1 + nt * 8) = make_float2(acc[nt][2], acc[nt][3]);
        }
    }
}

// ---------------------------------------------------------------------------
// CSR build (side stream)
// ---------------------------------------------------------------------------
__global__ void hist_kernel(const int* __restrict__ erow, int E) {
    int e = blockIdx.x * blockDim.x + threadIdx.x;
    if (e < E) atomicAdd(&g_cnt[erow[e]], 1);
}

__global__ void scan_kernel(int N) {
    __shared__ int wsum[32];
    __shared__ int carry;
    int t = threadIdx.x, lane = t & 31, w = t >> 5;
    if (t == 0) { carry = 0; g_rowptr[0] = 0; }
    __syncthreads();

    for (int base = 0; base < N; base += 1024) {
        int i = base + t;
        int v = (i < N) ? g_cnt[i] : 0;
        int s = v;
        #pragma unroll
        for (int off = 1; off < 32; off <<= 1) {
            int u = __shfl_up_sync(0xffffffffu, s, off);
            if (lane >= off) s += u;
        }
        if (lane == 31) wsum[w] = s;
        __syncthreads();
        if (w == 0) {
            int ws = wsum[lane];
            #pragma unroll
            for (int off = 1; off < 32; off <<= 1) {
                int u = __shfl_up_sync(0xffffffffu, ws, off);
                if (lane >= off) ws += u;
            }
            wsum[lane] = ws;
        }
        __syncthreads();
        int prefix = carry + (w ? wsum[w - 1] : 0);
        int incl = prefix + s;
        if (i < N) {
            g_rowptr[i + 1] = incl;
            g_cursor[i] = incl - v;
        }
        __syncthreads();
        if (t == 1023) carry = incl;
        __syncthreads();
    }
}

__global__ void fill_kernel(const int* __restrict__ erow,
                            const int* __restrict__ ecol,
                            const float* __restrict__ evals,
                            int E) {
    int e = blockIdx.x * blockDim.x + threadIdx.x;
    if (e < E) {
        int r = erow[e];
        int pos = atomicAdd(&g_cursor[r], 1);
        unsigned long long m = (unsigned long long)(unsigned)ecol[e]
                             | ((unsigned long long)__float_as_uint(evals[e]) << 32);
        g_csr[pos] = m;
    }
}

// ---------------------------------------------------------------------------
// Gather: out[b,r,:] = relu( sum_e val_e * y[b,col_e,:] + bias )
// One warp per node row r; 4 batches per warp.
// ---------------------------------------------------------------------------
__global__ void gather_kernel(const float* __restrict__ bias,
                              float* __restrict__ out,
                              int N) {
    int warp_global = (blockIdx.x * blockDim.x + threadIdx.x) >> 5;
    int lane = threadIdx.x & 31;
    if (warp_global >= N) return;
    int r = warp_global;

    float4 bv = ((const float4*)bias)[lane];

    int start = g_rowptr[r];
    int end   = g_rowptr[r + 1];

    float4 a0 = make_float4(0.f, 0.f, 0.f, 0.f);
    float4 a1 = a0, a2 = a0, a3 = a0;

    const size_t bstride = (size_t)N * GC;

    for (int e = start; e < end; e++) {
        unsigned long long m = g_csr[e];
        int col = (int)(m & 0xffffffffu);
        float v = __uint_as_float((unsigned)(m >> 32));

        const float* yc = g_y + (size_t)col * GC;
        float4 y0 = ((const float4*)(yc              ))[lane];
        float4 y1 = ((const float4*)(yc + bstride    ))[lane];
        float4 y2 = ((const float4*)(yc + 2 * bstride))[lane];
        float4 y3 = ((const float4*)(yc + 3 * bstride))[lane];

        a0.x += v * y0.x; a0.y += v * y0.y; a0.z += v * y0.z; a0.w += v * y0.w;
        a1.x += v * y1.x; a1.y += v * y1.y; a1.z += v * y1.z; a1.w += v * y1.w;
        a2.x += v * y2.x; a2.y += v * y2.y; a2.z += v * y2.z; a2.w += v * y2.w;
        a3.x += v * y3.x; a3.y += v * y3.y; a3.z += v * y3.z; a3.w += v * y3.w;
    }

    float4 o;
    float* dst = out + (size_t)r * GC;
    o.x = fmaxf(a0.x + bv.x, 0.f); o.y = fmaxf(a0.y + bv.y, 0.f);
    o.z = fmaxf(a0.z + bv.z, 0.f); o.w = fmaxf(a0.w + bv.w, 0.f);
    ((float4*)(dst))[lane] = o;
    o.x = fmaxf(a1.x + bv.x, 0.f); o.y = fmaxf(a1.y + bv.y, 0.f);
    o.z = fmaxf(a1.z + bv.z, 0.f); o.w = fmaxf(a1.w + bv.w, 0.f);
    ((float4*)(dst + bstride))[lane] = o;
    o.x = fmaxf(a2.x + bv.x, 0.f); o.y = fmaxf(a2.y + bv.y, 0.f);
    o.z = fmaxf(a2.z + bv.z, 0.f); o.w = fmaxf(a2.w + bv.w, 0.f);
    ((float4*)(dst + 2 * bstride))[lane] = o;
    o.x = fmaxf(a3.x + bv.x, 0.f); o.y = fmaxf(a3.y + bv.y, 0.f);
    o.z = fmaxf(a3.z + bv.z, 0.f); o.w = fmaxf(a3.w + bv.w, 0.f);
    ((float4*)(dst + 3 * bstride))[lane] = o;
}

// ---------------------------------------------------------------------------
// Launch. CSR build on side stream (overlapped with W prep + GEMM).
// Inputs: x [B,N,C], edge_row [E], edge_col [E], edge_vals [E], W [C,C], b [C]
// ---------------------------------------------------------------------------
extern "C" void kernel_launch(void* const* d_in, const int* in_sizes, int n_in,
                              void* d_out, int out_size) {
    const float* x     = (const float*)d_in[0];
    const int*   erow  = (const int*)d_in[1];
    const int*   ecol  = (const int*)d_in[2];
    const float* evals = (const float*)d_in[3];
    const float* W     = (const float*)d_in[4];
    const float* bias  = (const float*)d_in[5];
    float* out = (float*)d_out;

    int E = in_sizes[1];
    int N = in_sizes[0] / (GB * GC);
    int total_rows = out_size / GC;   // B*N
    int ntiles = (total_rows + TILE_M - 1) / TILE_M;

    const size_t smem_bytes = (size_t)4 * GC * APAD * sizeof(__nv_bfloat16); // 139264

    static cudaStream_t s_side = nullptr;
    static cudaEvent_t ev_fork = nullptr, ev_join = nullptr;
    if (s_side == nullptr) {
        cudaStreamCreateWithFlags(&s_side, cudaStreamNonBlocking);
        cudaEventCreateWithFlags(&ev_fork, cudaEventDisableTiming);
        cudaEventCreateWithFlags(&ev_join, cudaEventDisableTiming);
        cudaFuncSetAttribute(gemm_hmma_kernel,
                             cudaFuncAttributeMaxDynamicSharedMemorySize,
                             (int)smem_bytes);
    }

    void* cnt_ptr = nullptr;
    cudaGetSymbolAddress(&cnt_ptr, g_cnt);

    // --- fork: CSR build on side stream ---
    cudaEventRecord(ev_fork, 0);
    cudaStreamWaitEvent(s_side, ev_fork, 0);
    cudaMemsetAsync(cnt_ptr, 0, (size_t)N * sizeof(int), s_side);
    hist_kernel<<<(E + 255) / 256, 256, 0, s_side>>>(erow, E);
    scan_kernel<<<1, 1024, 0, s_side>>>(N);
    fill_kernel<<<(E + 255) / 256, 256, 0, s_side>>>(erow, ecol, evals, E);
    cudaEventRecord(ev_join, s_side);

    // --- main stream: W prep, then HMMA GEMM ---
    wprep_kernel<<<(GC * GC + 255) / 256, 256>>>(W);
    gemm_hmma_kernel<<<ntiles, 256, smem_bytes>>>(x, total_rows);

    // --- join, then gather ---
    cudaStreamWaitEvent(0, ev_join, 0);
    {
        int threads = 256;                 // 8 warps/block, 1 warp per row
        int blocks = (N + 7) / 8;
        gather_kernel<<<blocks, threads>>>(bias, out, N);
    }
}

// round 7
// speedup vs baseline: 4.3925x; 1.0523x over previous
#include <cuda_runtime.h>
#include <cuda_bf16.h>
#include <cstdint>

// Problem constants (B=4, N=50000, E=800000, C_IN=C_OUT=128)
#define GB 4
#define GC 128
#define MAXN 50000
#define MAXE 800000
#define TILE_M 128
#define APAD 136   // padded bf16 row (272B stride): conflict-free ldmatrix

// y = x @ W scratch (102.4 MB)
__device__ float g_y[(size_t)GB * MAXN * GC];
// CSR structures
__device__ int g_cnt[MAXN];
__device__ int g_rowptr[MAXN + 1];
__device__ int g_cursor[MAXN];
__device__ unsigned long long g_csr[MAXE];
// Pre-transposed, hi/lo-split W images: [n][k] bf16, padded to APAD
__device__ __align__(16) __nv_bfloat16 g_Whi[GC * APAD];
__device__ __align__(16) __nv_bfloat16 g_Wlo[GC * APAD];

// ---------------------------------------------------------------------------
// PTX helpers (base sm_103 target — no 'a' features)
// ---------------------------------------------------------------------------
__device__ __forceinline__ uint32_t smem_u32(const void* p) {
    uint32_t a;
    asm("{ .reg .u64 t; cvta.to.shared.u64 t, %1; cvt.u32.u64 %0, t; }"
        : "=r"(a) : "l"(p));
    return a;
}
__device__ __forceinline__ void ldsm4(uint32_t* r, uint32_t addr) {
    asm volatile("ldmatrix.sync.aligned.m8n8.x4.shared.b16 {%0,%1,%2,%3}, [%4];"
                 : "=r"(r[0]), "=r"(r[1]), "=r"(r[2]), "=r"(r[3]) : "r"(addr));
}
__device__ __forceinline__ void mma16816(float* d, const uint32_t* a, const uint32_t* b) {
    asm volatile("mma.sync.aligned.m16n8k16.row.col.f32.bf16.bf16.f32 "
                 "{%0,%1,%2,%3}, {%4,%5,%6,%7}, {%8,%9}, {%0,%1,%2,%3};"
                 : "+f"(d[0]), "+f"(d[1]), "+f"(d[2]), "+f"(d[3])
                 : "r"(a[0]), "r"(a[1]), "r"(a[2]), "r"(a[3]),
                   "r"(b[0]), "r"(b[1]));
}

// ---------------------------------------------------------------------------
// W prep: B[n][k] = W[k][n], split into bf16 hi + lo residual.
// ---------------------------------------------------------------------------
__global__ void wprep_kernel(const float* __restrict__ W) {
    int idx = blockIdx.x * blockDim.x + threadIdx.x;
    if (idx >= GC * GC) return;
    int n = idx >> 7, k = idx & 127;
    float v = W[k * GC + n];
    __nv_bfloat16 h = __float2bfloat16(v);
    __nv_bfloat16 l = __float2bfloat16(v - __bfloat162float(h));
    g_Whi[n * APAD + k] = h;
    g_Wlo[n * APAD + k] = l;
}

// ---------------------------------------------------------------------------
// HMMA GEMM over row range [row0, row_end): y = x @ W, 3-pass bf16 split.
// 256 threads, tile 128x128x128. Warp w: rows w*16..w*16+15, all 128 cols.
// ---------------------------------------------------------------------------
__global__ void __launch_bounds__(256, 1)
gemm_hmma_kernel(const float* __restrict__ x, int row0, int row_end) {
    extern __shared__ __nv_bfloat16 sm[];
    __nv_bfloat16* sAhi = sm;                  // 128 * APAD
    __nv_bfloat16* sAlo = sm + GC * APAD;
    __nv_bfloat16* sBhi = sm + 2 * GC * APAD;
    __nv_bfloat16* sBlo = sm + 3 * GC * APAD;

    int tid = threadIdx.x, wid = tid >> 5, lane = tid & 31;
    int row_base = row0 + blockIdx.x * TILE_M;

    // Copy pre-split W images
    {
        const uint4* sh = (const uint4*)g_Whi;
        const uint4* sl = (const uint4*)g_Wlo;
        uint4* dh = (uint4*)sBhi;
        uint4* dl = (uint4*)sBlo;
        for (int i = tid; i < (GC * APAD * 2) / 16; i += 256) {
            dh[i] = sh[i];
            dl[i] = sl[i];
        }
    }

    // Load A tile (128 x 128 f32), convert to bf16 hi/lo
    {
        const float4* src = (const float4*)(x + (size_t)row_base * GC);
        #pragma unroll
        for (int j = 0; j < 16; j++) {
            int i = tid + j * 256;
            int row = i >> 5, c4 = i & 31;
            float4 v = make_float4(0.f, 0.f, 0.f, 0.f);
            if (row_base + row < row_end) v = src[i];
            __nv_bfloat16 h0 = __float2bfloat16(v.x), h1 = __float2bfloat16(v.y);
            __nv_bfloat16 h2 = __float2bfloat16(v.z), h3 = __float2bfloat16(v.w);
            __nv_bfloat16 l0 = __float2bfloat16(v.x - __bfloat162float(h0));
            __nv_bfloat16 l1 = __float2bfloat16(v.y - __bfloat162float(h1));
            __nv_bfloat16 l2 = __float2bfloat16(v.z - __bfloat162float(h2));
            __nv_bfloat16 l3 = __float2bfloat16(v.w - __bfloat162float(h3));
            int off = row * APAD + c4 * 4;
            uint32_t hh0 = (uint32_t)__bfloat16_as_ushort(h0) | ((uint32_t)__bfloat16_as_ushort(h1) << 16);
            uint32_t hh1 = (uint32_t)__bfloat16_as_ushort(h2) | ((uint32_t)__bfloat16_as_ushort(h3) << 16);
            uint32_t ll0 = (uint32_t)__bfloat16_as_ushort(l0) | ((uint32_t)__bfloat16_as_ushort(l1) << 16);
            uint32_t ll1 = (uint32_t)__bfloat16_as_ushort(l2) | ((uint32_t)__bfloat16_as_ushort(l3) << 16);
            *(uint2*)(sAhi + off) = make_uint2(hh0, hh1);
            *(uint2*)(sAlo + off) = make_uint2(ll0, ll1);
        }
    }
    __syncthreads();

    int r0 = wid * 16;

    uint32_t aRowOff = ((uint32_t)(r0 + (lane & 15)) * APAD + (uint32_t)(lane >> 4) * 8) * 2;
    uint32_t aHiBase = smem_u32(sAhi) + aRowOff;
    uint32_t aLoBase = smem_u32(sAlo) + aRowOff;
    uint32_t bRowOff = ((uint32_t)((lane & 7) + ((lane >> 4) << 3)) * APAD
                        + (uint32_t)((lane >> 3) & 1) * 8) * 2;
    uint32_t bHi0 = smem_u32(sBhi) + bRowOff;
    uint32_t bLo0 = smem_u32(sBlo) + bRowOff;

    float acc[16][4];
    #pragma unroll
    for (int t = 0; t < 16; t++)
        #pragma unroll
        for (int j = 0; j < 4; j++) acc[t][j] = 0.f;

    #pragma unroll
    for (int ks = 0; ks < 8; ks++) {
        uint32_t ahi[4], alo[4];
        ldsm4(ahi, aHiBase + ks * 32);
        ldsm4(alo, aLoBase + ks * 32);
        #pragma unroll
        for (int nt2 = 0; nt2 < 8; nt2++) {
            uint32_t bhi[4], blo[4];
            uint32_t boff = (uint32_t)(nt2 * 16) * APAD * 2 + ks * 32;
            ldsm4(bhi, bHi0 + boff);
            ldsm4(blo, bLo0 + boff);
            mma16816(acc[nt2 * 2],     ahi, bhi);
            mma16816(acc[nt2 * 2 + 1], ahi, bhi + 2);
            mma16816(acc[nt2 * 2],     alo, bhi);
            mma16816(acc[nt2 * 2 + 1], alo, bhi + 2);
            mma16816(acc[nt2 * 2],     ahi, blo);
            mma16816(acc[nt2 * 2 + 1], ahi, blo + 2);
        }
    }

    {
        int rlo = r0 + (lane >> 2);
        int col = (lane & 3) * 2;
        long g0 = (long)row_base + rlo;
        long g1 = g0 + 8;
        float* y0 = g_y + (size_t)g0 * GC + col;
        float* y1 = g_y + (size_t)g1 * GC + col;
        bool ok0 = g0 < row_end, ok1 = g1 < row_end;
        #pragma unroll
        for (int nt = 0; nt < 16; nt++) {
            if (ok0) *(float2*)(y0 + nt * 8) = make_float2(acc[nt][0], acc[nt][1]);
            if (ok1) *(float2*)(y1 + nt * 8) = make_float2(acc[nt][2], acc[nt][3]);
        }
    }
}

// ---------------------------------------------------------------------------
// CSR build (side stream)
// ---------------------------------------------------------------------------
__global__ void hist_kernel(const int* __restrict__ erow, int E) {
    int e = blockIdx.x * blockDim.x + threadIdx.x;
    if (e < E) atomicAdd(&g_cnt[erow[e]], 1);
}

__global__ void scan_kernel(int N) {
    __shared__ int wsum[32];
    __shared__ int carry;
    int t = threadIdx.x, lane = t & 31, w = t >> 5;
    if (t == 0) { carry = 0; g_rowptr[0] = 0; }
    __syncthreads();

    for (int base = 0; base < N; base += 1024) {
        int i = base + t;
        int v = (i < N) ? g_cnt[i] : 0;
        int s = v;
        #pragma unroll
        for (int off = 1; off < 32; off <<= 1) {
            int u = __shfl_up_sync(0xffffffffu, s, off);
            if (lane >= off) s += u;
        }
        if (lane == 31) wsum[w] = s;
        __syncthreads();
        if (w == 0) {
            int ws = wsum[lane];
            #pragma unroll
            for (int off = 1; off < 32; off <<= 1) {
                int u = __shfl_up_sync(0xffffffffu, ws, off);
                if (lane >= off) ws += u;
            }
            wsum[lane] = ws;
        }
        __syncthreads();
        int prefix = carry + (w ? wsum[w - 1] : 0);
        int incl = prefix + s;
        if (i < N) {
            g_rowptr[i + 1] = incl;
            g_cursor[i] = incl - v;
        }
        __syncthreads();
        if (t == 1023) carry = incl;
        __syncthreads();
    }
}

__global__ void fill_kernel(const int* __restrict__ erow,
                            const int* __restrict__ ecol,
                            const float* __restrict__ evals,
                            int E) {
    int e = blockIdx.x * blockDim.x + threadIdx.x;
    if (e < E) {
        int r = erow[e];
        int pos = atomicAdd(&g_cursor[r], 1);
        unsigned long long m = (unsigned long long)(unsigned)ecol[e]
                             | ((unsigned long long)__float_as_uint(evals[e]) << 32);
        g_csr[pos] = m;
    }
}

// ---------------------------------------------------------------------------
// Per-batch gather: out[b,r,:] = relu( sum_e val_e * y[b,col_e,:] + bias )
// One warp per node row; 4-edge unroll for MLP.
// ---------------------------------------------------------------------------
__global__ void gather_b_kernel(const float* __restrict__ bias,
                                float* __restrict__ out,
                                int N, int b) {
    int r = (blockIdx.x * blockDim.x + threadIdx.x) >> 5;
    int lane = threadIdx.x & 31;
    if (r >= N) return;

    float4 bv = ((const float4*)bias)[lane];
    int e   = g_rowptr[r];
    int end = g_rowptr[r + 1];

    const float* yb = g_y + (size_t)b * N * GC;

    float4 a0 = make_float4(0.f, 0.f, 0.f, 0.f);
    float4 a1 = a0;

    for (; e + 4 <= end; e += 4) {
        unsigned long long m0 = g_csr[e];
        unsigned long long m1 = g_csr[e + 1];
        unsigned long long m2 = g_csr[e + 2];
        unsigned long long m3 = g_csr[e + 3];
        int   c0 = (int)(m0 & 0xffffffffu); float v0 = __uint_as_float((unsigned)(m0 >> 32));
        int   c1 = (int)(m1 & 0xffffffffu); float v1 = __uint_as_float((unsigned)(m1 >> 32));
        int   c2 = (int)(m2 & 0xffffffffu); float v2 = __uint_as_float((unsigned)(m2 >> 32));
        int   c3 = (int)(m3 & 0xffffffffu); float v3 = __uint_as_float((unsigned)(m3 >> 32));
        float4 y0 = ((const float4*)(yb + (size_t)c0 * GC))[lane];
        float4 y1 = ((const float4*)(yb + (size_t)c1 * GC))[lane];
        float4 y2 = ((const float4*)(yb + (size_t)c2 * GC))[lane];
        float4 y3 = ((const float4*)(yb + (size_t)c3 * GC))[lane];
        a0.x += v0 * y0.x; a0.y += v0 * y0.y; a0.z += v0 * y0.z; a0.w += v0 * y0.w;
        a1.x += v1 * y1.x; a1.y += v1 * y1.y; a1.z += v1 * y1.z; a1.w += v1 * y1.w;
        a0.x += v2 * y2.x; a0.y += v2 * y2.y; a0.z += v2 * y2.z; a0.w += v2 * y2.w;
        a1.x += v3 * y3.x; a1.y += v3 * y3.y; a1.z += v3 * y3.z; a1.w += v3 * y3.w;
    }
    for (; e < end; e++) {
        unsigned long long m = g_csr[e];
        int   c = (int)(m & 0xffffffffu);
        float v = __uint_as_float((unsigned)(m >> 32));
        float4 y = ((const float4*)(yb + (size_t)c * GC))[lane];
        a0.x += v * y.x; a0.y += v * y.y; a0.z += v * y.z; a0.w += v * y.w;
    }

    float4 o;
    o.x = fmaxf(a0.x + a1.x + bv.x, 0.f);
    o.y = fmaxf(a0.y + a1.y + bv.y, 0.f);
    o.z = fmaxf(a0.z + a1.z + bv.z, 0.f);
    o.w = fmaxf(a0.w + a1.w + bv.w, 0.f);
    ((float4*)(out + ((size_t)b * N + r) * GC))[lane] = o;
}

// ---------------------------------------------------------------------------
// Launch. CSR on side stream 1; GEMM per batch on main stream; gathers per
// batch on side stream 2, each overlapping the remaining GEMMs.
// Inputs: x [B,N,C], edge_row [E], edge_col [E], edge_vals [E], W [C,C], b [C]
// ---------------------------------------------------------------------------
extern "C" void kernel_launch(void* const* d_in, const int* in_sizes, int n_in,
                              void* d_out, int out_size) {
    const float* x     = (const float*)d_in[0];
    const int*   erow  = (const int*)d_in[1];
    const int*   ecol  = (const int*)d_in[2];
    const float* evals = (const float*)d_in[3];
    const float* W     = (const float*)d_in[4];
    const float* bias  = (const float*)d_in[5];
    float* out = (float*)d_out;

    int E = in_sizes[1];
    int N = in_sizes[0] / (GB * GC);

    const size_t smem_bytes = (size_t)4 * GC * APAD * sizeof(__nv_bfloat16); // 139264

    static cudaStream_t s_csr = nullptr, s_gat = nullptr;
    static cudaEvent_t ev_fork = nullptr, ev_csr = nullptr, ev_done = nullptr;
    static cudaEvent_t ev_gemm[GB] = {};
    if (s_csr == nullptr) {
        cudaStreamCreateWithFlags(&s_csr, cudaStreamNonBlocking);
        cudaStreamCreateWithFlags(&s_gat, cudaStreamNonBlocking);
        cudaEventCreateWithFlags(&ev_fork, cudaEventDisableTiming);
        cudaEventCreateWithFlags(&ev_csr, cudaEventDisableTiming);
        cudaEventCreateWithFlags(&ev_done, cudaEventDisableTiming);
        for (int b = 0; b < GB; b++)
            cudaEventCreateWithFlags(&ev_gemm[b], cudaEventDisableTiming);
        cudaFuncSetAttribute(gemm_hmma_kernel,
                             cudaFuncAttributeMaxDynamicSharedMemorySize,
                             (int)smem_bytes);
    }

    void* cnt_ptr = nullptr;
    cudaGetSymbolAddress(&cnt_ptr, g_cnt);

    // --- fork: CSR build on side stream ---
    cudaEventRecord(ev_fork, 0);
    cudaStreamWaitEvent(s_csr, ev_fork, 0);
    cudaMemsetAsync(cnt_ptr, 0, (size_t)N * sizeof(int), s_csr);
    hist_kernel<<<(E + 255) / 256, 256, 0, s_csr>>>(erow, E);
    scan_kernel<<<1, 1024, 0, s_csr>>>(N);
    fill_kernel<<<(E + 255) / 256, 256, 0, s_csr>>>(erow, ecol, evals, E);
    cudaEventRecord(ev_csr, s_csr);

    // --- main stream: W prep, then per-batch GEMM ---
    wprep_kernel<<<(GC * GC + 255) / 256, 256>>>(W);
    int ntb = (N + TILE_M - 1) / TILE_M;   // tiles per batch
    for (int b = 0; b < GB; b++) {
        gemm_hmma_kernel<<<ntb, 256, smem_bytes>>>(x, b * N, (b + 1) * N);
        cudaEventRecord(ev_gemm[b], 0);
    }

    // --- side stream 2: per-batch gathers, pipelined behind GEMMs ---
    cudaStreamWaitEvent(s_gat, ev_csr, 0);
    int gblocks = (N + 7) / 8;   // 8 warps/block, 1 warp per row
    for (int b = 0; b < GB; b++) {
        cudaStreamWaitEvent(s_gat, ev_gemm[b], 0);
        gather_b_kernel<<<gblocks, 256, 0, s_gat>>>(bias, out, N, b);
    }
    cudaEventRecord(ev_done, s_gat);
    cudaStreamWaitEvent(0, ev_done, 0);
}

// round 8
// speedup vs baseline: 4.9174x; 1.1195x over previous
#include <cuda_runtime.h>
#include <cuda_bf16.h>
#include <cuda_fp16.h>
#include <cstdint>

// Problem constants (B=4, N=50000, E=800000, C_IN=C_OUT=128)
#define GB 4
#define GC 128
#define MAXN 50000
#define MAXE 800000
#define TILE_M 128
#define APAD 136   // padded bf16 row (272B stride): conflict-free ldmatrix

// y = x @ W scratch, fp16 (51.2 MB -> fits L2)
__device__ __half g_y[(size_t)GB * MAXN * GC];
// CSR structures
__device__ int g_cnt[MAXN];
__device__ int g_rowptr[MAXN + 1];
__device__ int g_cursor[MAXN];
__device__ unsigned long long g_csr[MAXE];
// Pre-transposed, hi/lo-split W images: [n][k] bf16, padded to APAD
__device__ __align__(16) __nv_bfloat16 g_Whi[GC * APAD];
__device__ __align__(16) __nv_bfloat16 g_Wlo[GC * APAD];

// ---------------------------------------------------------------------------
// PTX helpers (base sm_103 target — no 'a' features)
// ---------------------------------------------------------------------------
__device__ __forceinline__ uint32_t smem_u32(const void* p) {
    uint32_t a;
    asm("{ .reg .u64 t; cvta.to.shared.u64 t, %1; cvt.u32.u64 %0, t; }"
        : "=r"(a) : "l"(p));
    return a;
}
__device__ __forceinline__ void ldsm4(uint32_t* r, uint32_t addr) {
    asm volatile("ldmatrix.sync.aligned.m8n8.x4.shared.b16 {%0,%1,%2,%3}, [%4];"
                 : "=r"(r[0]), "=r"(r[1]), "=r"(r[2]), "=r"(r[3]) : "r"(addr));
}
__device__ __forceinline__ void mma16816(float* d, const uint32_t* a, const uint32_t* b) {
    asm volatile("mma.sync.aligned.m16n8k16.row.col.f32.bf16.bf16.f32 "
                 "{%0,%1,%2,%3}, {%4,%5,%6,%7}, {%8,%9}, {%0,%1,%2,%3};"
                 : "+f"(d[0]), "+f"(d[1]), "+f"(d[2]), "+f"(d[3])
                 : "r"(a[0]), "r"(a[1]), "r"(a[2]), "r"(a[3]),
                   "r"(b[0]), "r"(b[1]));
}

// ---------------------------------------------------------------------------
// W prep: B[n][k] = W[k][n], split into bf16 hi + lo residual.
// ---------------------------------------------------------------------------
__global__ void wprep_kernel(const float* __restrict__ W) {
    int idx = blockIdx.x * blockDim.x + threadIdx.x;
    if (idx >= GC * GC) return;
    int n = idx >> 7, k = idx & 127;
    float v = W[k * GC + n];
    __nv_bfloat16 h = __float2bfloat16(v);
    __nv_bfloat16 l = __float2bfloat16(v - __bfloat162float(h));
    g_Whi[n * APAD + k] = h;
    g_Wlo[n * APAD + k] = l;
}

// ---------------------------------------------------------------------------
// HMMA GEMM over row range [row0, row_end): y = x @ W, 3-pass bf16 split,
// fp16 output. 256 threads, tile 128x128x128.
// ---------------------------------------------------------------------------
__global__ void __launch_bounds__(256, 1)
gemm_hmma_kernel(const float* __restrict__ x, int row0, int row_end) {
    extern __shared__ __nv_bfloat16 sm[];
    __nv_bfloat16* sAhi = sm;                  // 128 * APAD
    __nv_bfloat16* sAlo = sm + GC * APAD;
    __nv_bfloat16* sBhi = sm + 2 * GC * APAD;
    __nv_bfloat16* sBlo = sm + 3 * GC * APAD;

    int tid = threadIdx.x, wid = tid >> 5, lane = tid & 31;
    int row_base = row0 + blockIdx.x * TILE_M;

    // Copy pre-split W images
    {
        const uint4* sh = (const uint4*)g_Whi;
        const uint4* sl = (const uint4*)g_Wlo;
        uint4* dh = (uint4*)sBhi;
        uint4* dl = (uint4*)sBlo;
        for (int i = tid; i < (GC * APAD * 2) / 16; i += 256) {
            dh[i] = sh[i];
            dl[i] = sl[i];
        }
    }

    // Load A tile (128 x 128 f32), convert to bf16 hi/lo
    {
        const float4* src = (const float4*)(x + (size_t)row_base * GC);
        #pragma unroll
        for (int j = 0; j < 16; j++) {
            int i = tid + j * 256;
            int row = i >> 5, c4 = i & 31;
            float4 v = make_float4(0.f, 0.f, 0.f, 0.f);
            if (row_base + row < row_end) v = src[i];
            __nv_bfloat16 h0 = __float2bfloat16(v.x), h1 = __float2bfloat16(v.y);
            __nv_bfloat16 h2 = __float2bfloat16(v.z), h3 = __float2bfloat16(v.w);
            __nv_bfloat16 l0 = __float2bfloat16(v.x - __bfloat162float(h0));
            __nv_bfloat16 l1 = __float2bfloat16(v.y - __bfloat162float(h1));
            __nv_bfloat16 l2 = __float2bfloat16(v.z - __bfloat162float(h2));
            __nv_bfloat16 l3 = __float2bfloat16(v.w - __bfloat162float(h3));
            int off = row * APAD + c4 * 4;
            uint32_t hh0 = (uint32_t)__bfloat16_as_ushort(h0) | ((uint32_t)__bfloat16_as_ushort(h1) << 16);
            uint32_t hh1 = (uint32_t)__bfloat16_as_ushort(h2) | ((uint32_t)__bfloat16_as_ushort(h3) << 16);
            uint32_t ll0 = (uint32_t)__bfloat16_as_ushort(l0) | ((uint32_t)__bfloat16_as_ushort(l1) << 16);
            uint32_t ll1 = (uint32_t)__bfloat16_as_ushort(l2) | ((uint32_t)__bfloat16_as_ushort(l3) << 16);
            *(uint2*)(sAhi + off) = make_uint2(hh0, hh1);
            *(uint2*)(sAlo + off) = make_uint2(ll0, ll1);
        }
    }
    __syncthreads();

    int r0 = wid * 16;

    uint32_t aRowOff = ((uint32_t)(r0 + (lane & 15)) * APAD + (uint32_t)(lane >> 4) * 8) * 2;
    uint32_t aHiBase = smem_u32(sAhi) + aRowOff;
    uint32_t aLoBase = smem_u32(sAlo) + aRowOff;
    uint32_t bRowOff = ((uint32_t)((lane & 7) + ((lane >> 4) << 3)) * APAD
                        + (uint32_t)((lane >> 3) & 1) * 8) * 2;
    uint32_t bHi0 = smem_u32(sBhi) + bRowOff;
    uint32_t bLo0 = smem_u32(sBlo) + bRowOff;

    float acc[16][4];
    #pragma unroll
    for (int t = 0; t < 16; t++)
        #pragma unroll
        for (int j = 0; j < 4; j++) acc[t][j] = 0.f;

    #pragma unroll
    for (int ks = 0; ks < 8; ks++) {
        uint32_t ahi[4], alo[4];
        ldsm4(ahi, aHiBase + ks * 32);
        ldsm4(alo, aLoBase + ks * 32);
        #pragma unroll
        for (int nt2 = 0; nt2 < 8; nt2++) {
            uint32_t bhi[4], blo[4];
            uint32_t boff = (uint32_t)(nt2 * 16) * APAD * 2 + ks * 32;
            ldsm4(bhi, bHi0 + boff);
            ldsm4(blo, bLo0 + boff);
            mma16816(acc[nt2 * 2],     ahi, bhi);
            mma16816(acc[nt2 * 2 + 1], ahi, bhi + 2);
            mma16816(acc[nt2 * 2],     alo, bhi);
            mma16816(acc[nt2 * 2 + 1], alo, bhi + 2);
            mma16816(acc[nt2 * 2],     ahi, blo);
            mma16816(acc[nt2 * 2 + 1], ahi, blo + 2);
        }
    }

    // Epilogue: fp16 stores. d0,d1 -> row r0+lane/4 cols nt*8+(lane%4)*2;
    //           d2,d3 -> row +8.
    {
        int rlo = r0 + (lane >> 2);
        int col = (lane & 3) * 2;
        long g0 = (long)row_base + rlo;
        long g1 = g0 + 8;
        __half* y0 = g_y + (size_t)g0 * GC + col;
        __half* y1 = g_y + (size_t)g1 * GC + col;
        bool ok0 = g0 < row_end, ok1 = g1 < row_end;
        #pragma unroll
        for (int nt = 0; nt < 16; nt++) {
            if (ok0) *(__half2*)(y0 + nt * 8) =
                __floats2half2_rn(acc[nt][0], acc[nt][1]);
            if (ok1) *(__half2*)(y1 + nt * 8) =
                __floats2half2_rn(acc[nt][2], acc[nt][3]);
        }
    }
}

// ---------------------------------------------------------------------------
// CSR build (side stream)
// ---------------------------------------------------------------------------
__global__ void hist_kernel(const int* __restrict__ erow, int E) {
    int e = blockIdx.x * blockDim.x + threadIdx.x;
    if (e < E) atomicAdd(&g_cnt[erow[e]], 1);
}

__global__ void scan_kernel(int N) {
    __shared__ int wsum[32];
    __shared__ int carry;
    int t = threadIdx.x, lane = t & 31, w = t >> 5;
    if (t == 0) { carry = 0; g_rowptr[0] = 0; }
    __syncthreads();

    for (int base = 0; base < N; base += 1024) {
        int i = base + t;
        int v = (i < N) ? g_cnt[i] : 0;
        int s = v;
        #pragma unroll
        for (int off = 1; off < 32; off <<= 1) {
            int u = __shfl_up_sync(0xffffffffu, s, off);
            if (lane >= off) s += u;
        }
        if (lane == 31) wsum[w] = s;
        __syncthreads();
        if (w == 0) {
            int ws = wsum[lane];
            #pragma unroll
            for (int off = 1; off < 32; off <<= 1) {
                int u = __shfl_up_sync(0xffffffffu, ws, off);
                if (lane >= off) ws += u;
            }
            wsum[lane] = ws;
        }
        __syncthreads();
        int prefix = carry + (w ? wsum[w - 1] : 0);
        int incl = prefix + s;
        if (i < N) {
            g_rowptr[i + 1] = incl;
            g_cursor[i] = incl - v;
        }
        __syncthreads();
        if (t == 1023) carry = incl;
        __syncthreads();
    }
}

__global__ void fill_kernel(const int* __restrict__ erow,
                            const int* __restrict__ ecol,
                            const float* __restrict__ evals,
                            int E) {
    int e = blockIdx.x * blockDim.x + threadIdx.x;
    if (e < E) {
        int r = erow[e];
        int pos = atomicAdd(&g_cursor[r], 1);
        unsigned long long m = (unsigned long long)(unsigned)ecol[e]
                             | ((unsigned long long)__float_as_uint(evals[e]) << 32);
        g_csr[pos] = m;
    }
}

// ---------------------------------------------------------------------------
// Per-batch gather: out[b,r,:] = relu( sum_e val_e * y16[b,col_e,:] + bias )
// One warp per node row; 4-edge unroll; fp16 y, fp32 accumulate.
// ---------------------------------------------------------------------------
__device__ __forceinline__ void acc_half8(float4& a, float v, uint2 u) {
    float2 f0 = __half22float2(*(__half2*)&u.x);
    float2 f1 = __half22float2(*(__half2*)&u.y);
    a.x += v * f0.x; a.y += v * f0.y;
    a.z += v * f1.x; a.w += v * f1.y;
}

__global__ void gather_b_kernel(const float* __restrict__ bias,
                                float* __restrict__ out,
                                int N, int b) {
    int r = (blockIdx.x * blockDim.x + threadIdx.x) >> 5;
    int lane = threadIdx.x & 31;
    if (r >= N) return;

    float4 bv = ((const float4*)bias)[lane];
    int e   = g_rowptr[r];
    int end = g_rowptr[r + 1];

    const __half* yb = g_y + (size_t)b * N * GC;

    float4 a0 = make_float4(0.f, 0.f, 0.f, 0.f);
    float4 a1 = a0;

    for (; e + 4 <= end; e += 4) {
        unsigned long long m0 = g_csr[e];
        unsigned long long m1 = g_csr[e + 1];
        unsigned long long m2 = g_csr[e + 2];
        unsigned long long m3 = g_csr[e + 3];
        int   c0 = (int)(m0 & 0xffffffffu); float v0 = __uint_as_float((unsigned)(m0 >> 32));
        int   c1 = (int)(m1 & 0xffffffffu); float v1 = __uint_as_float((unsigned)(m1 >> 32));
        int   c2 = (int)(m2 & 0xffffffffu); float v2 = __uint_as_float((unsigned)(m2 >> 32));
        int   c3 = (int)(m3 & 0xffffffffu); float v3 = __uint_as_float((unsigned)(m3 >> 32));
        uint2 u0 = ((const uint2*)(yb + (size_t)c0 * GC))[lane];
        uint2 u1 = ((const uint2*)(yb + (size_t)c1 * GC))[lane];
        uint2 u2 = ((const uint2*)(yb + (size_t)c2 * GC))[lane];
        uint2 u3 = ((const uint2*)(yb + (size_t)c3 * GC))[lane];
        acc_half8(a0, v0, u0);
        acc_half8(a1, v1, u1);
        acc_half8(a0, v2, u2);
        acc_half8(a1, v3, u3);
    }
    for (; e < end; e++) {
        unsigned long long m = g_csr[e];
        int   c = (int)(m & 0xffffffffu);
        float v = __uint_as_float((unsigned)(m >> 32));
        uint2 u = ((const uint2*)(yb + (size_t)c * GC))[lane];
        acc_half8(a0, v, u);
    }

    // Lane covers cols lane*4 .. lane*4+3 (uint2 = 4 halfs)
    float4 o;
    o.x = fmaxf(a0.x + a1.x + bv.x, 0.f);
    o.y = fmaxf(a0.y + a1.y + bv.y, 0.f);
    o.z = fmaxf(a0.z + a1.z + bv.z, 0.f);
    o.w = fmaxf(a0.w + a1.w + bv.w, 0.f);
    ((float4*)(out + ((size_t)b * N + r) * GC))[lane] = o;
}

// ---------------------------------------------------------------------------
// Launch. CSR on side stream 1; GEMM per batch on main stream; gathers per
// batch on side stream 2, pipelined behind the GEMMs.
// Inputs: x [B,N,C], edge_row [E], edge_col [E], edge_vals [E], W [C,C], b [C]
// ---------------------------------------------------------------------------
extern "C" void kernel_launch(void* const* d_in, const int* in_sizes, int n_in,
                              void* d_out, int out_size) {
    const float* x     = (const float*)d_in[0];
    const int*   erow  = (const int*)d_in[1];
    const int*   ecol  = (const int*)d_in[2];
    const float* evals = (const float*)d_in[3];
    const float* W     = (const float*)d_in[4];
    const float* bias  = (const float*)d_in[5];
    float* out = (float*)d_out;

    int E = in_sizes[1];
    int N = in_sizes[0] / (GB * GC);

    const size_t smem_bytes = (size_t)4 * GC * APAD * sizeof(__nv_bfloat16); // 139264

    static cudaStream_t s_csr = nullptr, s_gat = nullptr;
    static cudaEvent_t ev_fork = nullptr, ev_csr = nullptr, ev_done = nullptr;
    static cudaEvent_t ev_gemm[GB] = {};
    if (s_csr == nullptr) {
        cudaStreamCreateWithFlags(&s_csr, cudaStreamNonBlocking);
        cudaStreamCreateWithFlags(&s_gat, cudaStreamNonBlocking);
        cudaEventCreateWithFlags(&ev_fork, cudaEventDisableTiming);
        cudaEventCreateWithFlags(&ev_csr, cudaEventDisableTiming);
        cudaEventCreateWithFlags(&ev_done, cudaEventDisableTiming);
        for (int b = 0; b < GB; b++)
            cudaEventCreateWithFlags(&ev_gemm[b], cudaEventDisableTiming);
        cudaFuncSetAttribute(gemm_hmma_kernel,
                             cudaFuncAttributeMaxDynamicSharedMemorySize,
                             (int)smem_bytes);
    }

    void* cnt_ptr = nullptr;
    cudaGetSymbolAddress(&cnt_ptr, g_cnt);

    // --- fork: CSR build on side stream ---
    cudaEventRecord(ev_fork, 0);
    cudaStreamWaitEvent(s_csr, ev_fork, 0);
    cudaMemsetAsync(cnt_ptr, 0, (size_t)N * sizeof(int), s_csr);
    hist_kernel<<<(E + 255) / 256, 256, 0, s_csr>>>(erow, E);
    scan_kernel<<<1, 1024, 0, s_csr>>>(N);
    fill_kernel<<<(E + 255) / 256, 256, 0, s_csr>>>(erow, ecol, evals, E);
    cudaEventRecord(ev_csr, s_csr);

    // --- main stream: W prep, then per-batch GEMM ---
    wprep_kernel<<<(GC * GC + 255) / 256, 256>>>(W);
    int ntb = (N + TILE_M - 1) / TILE_M;   // tiles per batch
    for (int b = 0; b < GB; b++) {
        gemm_hmma_kernel<<<ntb, 256, smem_bytes>>>(x, b * N, (b + 1) * N);
        cudaEventRecord(ev_gemm[b], 0);
    }

    // --- side stream 2: per-batch gathers, pipelined behind GEMMs ---
    cudaStreamWaitEvent(s_gat, ev_csr, 0);
    int gblocks = (N + 7) / 8;   // 8 warps/block, 1 warp per row
    for (int b = 0; b < GB; b++) {
        cudaStreamWaitEvent(s_gat, ev_gemm[b], 0);
        gather_b_kernel<<<gblocks, 256, 0, s_gat>>>(bias, out, N, b);
    }
    cudaEventRecord(ev_done, s_gat);
    cudaStreamWaitEvent(0, ev_done, 0);
}